// round 8
// baseline (speedup 1.0000x reference)
#include <cuda_runtime.h>
#include <cstdint>

// Sparse ConvTranspose3d on GB300 (sm_103a) — mma.sync tf32 tensor cores.
//   out[r,:] = bias + sum_{(k,n): out_index[k,n]==r} feats[n,:] @ weight[k,:,:]^T
//
// R8: 256 threads / 8 warps per 128-pt tile (1 m16 tile per warp) -> regs ~halve,
// occupancy ~2x, epilogue latency covered by warp parallelism.
// W[k] double-buffered in SMEM (reg prefetch under MMA); counts-split epilogue:
// count==1 -> streaming store of acc+bias, else red.global.add.v2.f32 onto
// conditionally bias-initialized rows.

#define CIN    64
#define COUT   64
#define TILE_N 128
#define KCHUNK 9
#define LDA    68          // padded row stride (floats)
#define MAX_ROWS (60000 * 27)

__device__ int g_counts[MAX_ROWS];

// ---------------------------------------------------------------- pre-pass ----
__global__ void zero_counts_kernel(int n4) {
    int i = blockIdx.x * blockDim.x + threadIdx.x;
    if (i < n4) reinterpret_cast<int4*>(g_counts)[i] = make_int4(0, 0, 0, 0);
}
__global__ void count_kernel(const int* __restrict__ oi, int total) {
    int i = blockIdx.x * blockDim.x + threadIdx.x;
    if (i < total) atomicAdd(&g_counts[oi[i]], 1);
}
// init rows whose count != 1 (count==0: pure bias; count>=2: bias base for atomics)
__global__ void cond_bias_init_kernel(const float4* __restrict__ bias4,
                                      float4* __restrict__ out4, int n_out) {
    int r = blockIdx.x * blockDim.x + threadIdx.x;
    if (r < n_out && g_counts[r] != 1) {
        #pragma unroll
        for (int j = 0; j < 16; j++) out4[(size_t)r * 16 + j] = bias4[j];
    }
}

// ---------------------------------------------------------------- helpers ----
__device__ __forceinline__ uint32_t to_tf32(float f) {
    uint32_t u;
    asm("cvt.rna.tf32.f32 %0, %1;" : "=r"(u) : "f"(f));
    return u;
}
__device__ __forceinline__ uint32_t f2u(float f) { return __float_as_uint(f); }

__device__ __forceinline__ void mma_tf32(float c[4], const uint32_t a[4],
                                         uint32_t b0, uint32_t b1) {
    asm volatile(
        "mma.sync.aligned.m16n8k8.row.col.f32.tf32.tf32.f32 "
        "{%0,%1,%2,%3}, {%4,%5,%6,%7}, {%8,%9}, {%0,%1,%2,%3};"
        : "+f"(c[0]), "+f"(c[1]), "+f"(c[2]), "+f"(c[3])
        : "r"(a[0]), "r"(a[1]), "r"(a[2]), "r"(a[3]), "r"(b0), "r"(b1));
}

__device__ __forceinline__ void st_cs_v2(float* p, float x, float y) {
    asm volatile("st.global.cs.v2.f32 [%0], {%1, %2};"
                 :: "l"(p), "f"(x), "f"(y) : "memory");
}

// ------------------------------------------------------------- main kernel ----
__global__ void __launch_bounds__(256, 2) spconvt_mma_kernel(
    const float* __restrict__ feats,     // [N, 64]
    const float* __restrict__ weight,    // [27, 64, 64]
    const float* __restrict__ bias,      // [64]
    const int*   __restrict__ out_index, // [27, N]
    float*       __restrict__ out,       // [n_out, 64]
    int N, int KV)
{
    extern __shared__ float smem[];
    float* As = smem;                        // 128 x 68
    float* Wb = smem + TILE_N * LDA;         // 2 x (64 x 68)

    const int tid  = threadIdx.x;
    const int w    = tid >> 5;               // warp 0..7
    const int lane = tid & 31;
    const int g    = lane >> 2;              // group 0..7
    const int t    = lane & 3;               // thread-in-group 0..3
    const int n0   = blockIdx.x * TILE_N;
    const int k0   = blockIdx.y * KCHUNK;

    // ---- A tile: LDG -> cvt.rna.tf32 -> padded SMEM (2048 float4, 8 iters) ----
    const float4* f4 = reinterpret_cast<const float4*>(feats);
    #pragma unroll
    for (int j = 0; j < 8; j++) {
        int idx = tid + 256 * j;              // 0..2047
        int p = idx >> 4, q = idx & 15;
        int n = n0 + p;
        float4 v = make_float4(0.f, 0.f, 0.f, 0.f);
        if (n < N) v = f4[(size_t)n * 16 + q];
        float* dst = As + p * LDA + q * 4;
        dst[0] = __uint_as_float(to_tf32(v.x));
        dst[1] = __uint_as_float(to_tf32(v.y));
        dst[2] = __uint_as_float(to_tf32(v.z));
        dst[3] = __uint_as_float(to_tf32(v.w));
    }
    // ---- W[k0] -> buf0 (1024 float4, 4 iters) ----
    {
        const float4* ws = reinterpret_cast<const float4*>(weight + (size_t)k0 * COUT * CIN);
        #pragma unroll
        for (int j = 0; j < 4; j++) {
            int idx = tid + 256 * j;          // 0..1023
            int c = idx >> 4, q = idx & 15;
            float4 v = ws[idx];
            float* dst = Wb + c * LDA + q * 4;
            dst[0] = __uint_as_float(to_tf32(v.x));
            dst[1] = __uint_as_float(to_tf32(v.y));
            dst[2] = __uint_as_float(to_tf32(v.z));
            dst[3] = __uint_as_float(to_tf32(v.w));
        }
    }

    // per-thread bias pairs: bias[8*nt + 2t .. +1]
    float2 b2[8];
    #pragma unroll
    for (int nt = 0; nt < 8; nt++)
        b2[nt] = __ldg(reinterpret_cast<const float2*>(bias) + nt * 4 + t);

    __syncthreads();

    const int pr = 16 * w + g;                // first owned point row (and pr+8)
    int buf = 0;

    for (int kk = 0; kk < KCHUNK; kk++) {
        int k = k0 + kk;
        if (k >= KV) break;
        bool more = (kk + 1 < KCHUNK) && (k + 1 < KV);

        // prefetch W[k+1] into regs (latency hidden under MMA loop)
        float4 wreg[4];
        if (more) {
            const float4* ws = reinterpret_cast<const float4*>(
                weight + (size_t)(k + 1) * COUT * CIN);
            #pragma unroll
            for (int j = 0; j < 4; j++) wreg[j] = ws[tid + 256 * j];
        }
        // prefetch scatter metadata for the 2 owned rows
        int rrv[2], cntv[2];
        #pragma unroll
        for (int j = 0; j < 2; j++) {
            int n = n0 + pr + 8 * j;
            rrv[j]  = (n < N) ? __ldg(out_index + (size_t)k * N + n) : -1;
            cntv[j] = (rrv[j] >= 0) ? __ldg(&g_counts[rrv[j]]) : 0;
        }

        const float* Wc = Wb + buf * (COUT * LDA);

        float acc[8][4];
        #pragma unroll
        for (int nt = 0; nt < 8; nt++)
            #pragma unroll
            for (int x = 0; x < 4; x++) acc[nt][x] = 0.f;

        #pragma unroll
        for (int kc = 0; kc < 8; kc++) {
            const int kb = kc * 8;
            uint32_t a[4];
            a[0] = f2u(As[(pr)     * LDA + kb + t]);
            a[1] = f2u(As[(pr + 8) * LDA + kb + t]);
            a[2] = f2u(As[(pr)     * LDA + kb + t + 4]);
            a[3] = f2u(As[(pr + 8) * LDA + kb + t + 4]);
            #pragma unroll
            for (int nt = 0; nt < 8; nt++) {
                int c = 8 * nt + g;
                uint32_t b0 = f2u(Wc[c * LDA + kb + t]);
                uint32_t b1 = f2u(Wc[c * LDA + kb + t + 4]);
                mma_tf32(acc[nt], a, b0, b1);
            }
        }

        // stage W[k+1] into the other buffer
        if (more) {
            float* dstb = Wb + (buf ^ 1) * (COUT * LDA);
            #pragma unroll
            for (int j = 0; j < 4; j++) {
                int idx = tid + 256 * j;
                int c = idx >> 4, q = idx & 15;
                float* dst = dstb + c * LDA + q * 4;
                dst[0] = __uint_as_float(to_tf32(wreg[j].x));
                dst[1] = __uint_as_float(to_tf32(wreg[j].y));
                dst[2] = __uint_as_float(to_tf32(wreg[j].z));
                dst[3] = __uint_as_float(to_tf32(wreg[j].w));
            }
        }

        // ---- scatter epilogue: rows pr (acc[.][0..1]) and pr+8 (acc[.][2..3]) ----
        #pragma unroll
        for (int j = 0; j < 2; j++) {
            if (rrv[j] < 0) continue;
            const int hi = j * 2;
            float* dst = out + (size_t)rrv[j] * COUT + 2 * t;
            if (cntv[j] == 1) {
                #pragma unroll
                for (int nt = 0; nt < 8; nt++)
                    st_cs_v2(dst + 8 * nt,
                             acc[nt][hi] + b2[nt].x, acc[nt][hi + 1] + b2[nt].y);
            } else {
                #pragma unroll
                for (int nt = 0; nt < 8; nt++) {
                    asm volatile("red.global.add.v2.f32 [%0], {%1, %2};"
                                 :: "l"(dst + 8 * nt),
                                    "f"(acc[nt][hi]), "f"(acc[nt][hi + 1])
                                 : "memory");
                }
            }
        }

        __syncthreads();      // all warps done with buf; W[k+1] visible
        buf ^= 1;
    }
}

extern "C" void kernel_launch(void* const* d_in, const int* in_sizes, int n_in,
                              void* d_out, int out_size) {
    const float* feats     = (const float*)d_in[0];   // [N, 64]
    const float* weight    = (const float*)d_in[1];   // [27, 64, 64]
    const float* bias      = (const float*)d_in[2];   // [64]
    const int*   out_index = (const int*)d_in[3];     // [27, N]
    float* out = (float*)d_out;                        // [n_out, 64]

    int N  = in_sizes[0] / CIN;
    int KV = in_sizes[1] / (COUT * CIN);
    int n_out = out_size / COUT;
    int total_idx = in_sizes[3];                       // KV * N

    int z4 = (n_out + 3) / 4;
    zero_counts_kernel<<<(z4 + 255) / 256, 256>>>(z4);
    count_kernel<<<(total_idx + 255) / 256, 256>>>(out_index, total_idx);
    cond_bias_init_kernel<<<(n_out + 255) / 256, 256>>>(
        (const float4*)bias, (float4*)out, n_out);

    const int smem_bytes = (TILE_N * LDA + 2 * COUT * LDA) * sizeof(float); // ~68KB
    cudaFuncSetAttribute(spconvt_mma_kernel,
                         cudaFuncAttributeMaxDynamicSharedMemorySize, smem_bytes);
    dim3 grid((N + TILE_N - 1) / TILE_N, (KV + KCHUNK - 1) / KCHUNK);
    spconvt_mma_kernel<<<grid, 256, smem_bytes>>>(feats, weight, bias, out_index,
                                                  out, N, KV);
}